// round 7
// baseline (speedup 1.0000x reference)
#include <cuda_runtime.h>
#include <math.h>

// Problem dims
#define BB 32
#define SS 64
#define TT 64
#define HID 512
#define G4 2048      // 4*HID
#define EMB 256
#define VSZ 32000
#define TD 63        // decoder steps (T-1)

// ---------------- device scratch (static, no allocations) ----------------
__device__ float d_Esrc[SS*BB*EMB];        // gathered encoder embeddings, row n = s*32+b
__device__ float d_Etgt[TD*BB*EMB];        // gathered decoder embeddings, row n = t*32+b
__device__ float d_Xf[SS*BB*G4];           // x@Wih_f.T + b_f
__device__ float d_Xb[SS*BB*G4];           // x@Wih_b.T + b_b
__device__ float d_Xd[TD*BB*G4];           // e@dWih[:, :256].T + db
__device__ float d_Xc[BB*G4];              // ctx@dWih[:,256:].T (constant across steps)
__device__ float d_hcat[BB*SS*2*HID];      // [b*64+s][fwd 512 | bwd 512]
__device__ float d_henc[2][BB*2*HID];      // double-buffered encoder h (fwd|bwd per row)
__device__ float d_cenc[BB*2*HID];
__device__ float d_hdec[2][BB*HID];
__device__ float d_cdec[BB*HID];
__device__ float d_encout[BB*SS*HID];      // enc_out, row n = b*64+s
__device__ float d_score[BB*SS];
__device__ float d_ctx[BB*HID];
__device__ float d_Hs[TD*BB*HID];          // decoder hidden states, row n = t*32+b
__device__ int   d_rowoff[TD*BB];

__device__ __forceinline__ float sigf(float x) { return 1.0f / (1.0f + expf(-x)); }

// ---------------- generic 64x64 tiled GEMM: C = A @ W^T (+bias) ----------------
// A: M x K (lda), W: N x K (ldw), C row m at (rowoff ? rowoff[m] : m*ldc), N = gridDim.x*64 exact.
__global__ __launch_bounds__(256) void gemm64(
    const float* __restrict__ A, int lda,
    const float* __restrict__ W, int ldw,
    const float* __restrict__ bias,
    float* __restrict__ C, int ldc,
    const int* __restrict__ rowoff,
    int M, int K, int act)
{
    __shared__ float As[16][68];
    __shared__ float Bs[16][68];
    int tid = threadIdx.x;
    int m0 = blockIdx.y << 6;
    int n0 = blockIdx.x << 6;
    int lrow = tid >> 2;          // 0..63
    int lk   = (tid & 3) << 2;    // 0,4,8,12
    int tx = tid & 15, ty = tid >> 4;

    float acc[4][4];
#pragma unroll
    for (int i = 0; i < 4; i++)
#pragma unroll
        for (int j = 0; j < 4; j++) acc[i][j] = 0.0f;

    const float* Ap = A + (size_t)(m0 + lrow) * lda + lk;
    const float* Wp = W + (size_t)(n0 + lrow) * ldw + lk;
    bool aok = (m0 + lrow) < M;

    for (int k0 = 0; k0 < K; k0 += 16) {
        float4 av = aok ? *(const float4*)(Ap + k0) : make_float4(0.f, 0.f, 0.f, 0.f);
        float4 bv = *(const float4*)(Wp + k0);
        __syncthreads();
        As[lk + 0][lrow] = av.x; As[lk + 1][lrow] = av.y; As[lk + 2][lrow] = av.z; As[lk + 3][lrow] = av.w;
        Bs[lk + 0][lrow] = bv.x; Bs[lk + 1][lrow] = bv.y; Bs[lk + 2][lrow] = bv.z; Bs[lk + 3][lrow] = bv.w;
        __syncthreads();
#pragma unroll
        for (int kk = 0; kk < 16; kk++) {
            float4 a = *(const float4*)&As[kk][ty << 2];
            float4 b = *(const float4*)&Bs[kk][tx << 2];
            acc[0][0] += a.x*b.x; acc[0][1] += a.x*b.y; acc[0][2] += a.x*b.z; acc[0][3] += a.x*b.w;
            acc[1][0] += a.y*b.x; acc[1][1] += a.y*b.y; acc[1][2] += a.y*b.z; acc[1][3] += a.y*b.w;
            acc[2][0] += a.z*b.x; acc[2][1] += a.z*b.y; acc[2][2] += a.z*b.z; acc[2][3] += a.z*b.w;
            acc[3][0] += a.w*b.x; acc[3][1] += a.w*b.y; acc[3][2] += a.w*b.z; acc[3][3] += a.w*b.w;
        }
    }

    int n = n0 + (tx << 2);
    float4 bz = make_float4(0.f, 0.f, 0.f, 0.f);
    if (bias) bz = *(const float4*)(bias + n);
#pragma unroll
    for (int r = 0; r < 4; r++) {
        int m = m0 + (ty << 2) + r;
        if (m < M) {
            float4 v;
            v.x = acc[r][0] + bz.x;
            v.y = acc[r][1] + bz.y;
            v.z = acc[r][2] + bz.z;
            v.w = acc[r][3] + bz.w;
            if (act) { v.x = tanhf(v.x); v.y = tanhf(v.y); v.z = tanhf(v.z); v.w = tanhf(v.w); }
            size_t base = rowoff ? (size_t)rowoff[m] : (size_t)m * (size_t)ldc;
            *(float4*)(C + base + n) = v;
        }
    }
}

// ---------------- small helper kernels ----------------
__global__ void zero_f(float* p, int n) {
    int i = blockIdx.x * blockDim.x + threadIdx.x;
    if (i < n) p[i] = 0.0f;
}

__global__ void zero_out0(float* out) {
    int i = blockIdx.x * blockDim.x + threadIdx.x;
    if (i < BB * VSZ) {
        int b = i / VSZ, v = i - b * VSZ;
        out[(size_t)b * TT * VSZ + v] = 0.0f;
    }
}

__global__ void rowoff_kernel() {
    int i = blockIdx.x * blockDim.x + threadIdx.x;
    if (i < TD * BB) {
        int t = i >> 5, b = i & 31;
        d_rowoff[i] = b * (TT * VSZ) + (t + 1) * VSZ;
    }
}

// 64 threads, one block per row: copy one embedding row (256 floats = 64 float4)
__global__ void gather_src(const int* __restrict__ src, const float* __restrict__ emb) {
    int n = blockIdx.x;           // n = s*32 + b
    int s = n >> 5, b = n & 31;
    int tok = src[b * SS + s];
    const float4* e = (const float4*)(emb + (size_t)tok * EMB);
    float4* d = (float4*)(d_Esrc + (size_t)n * EMB);
    d[threadIdx.x] = e[threadIdx.x];
}

__global__ void gather_tgt(const int* __restrict__ tgt, const float* __restrict__ emb) {
    int n = blockIdx.x;           // n = t*32 + b, t in 0..62
    int t = n >> 5, b = n & 31;
    int tok = tgt[b * TT + t];
    const float4* e = (const float4*)(emb + (size_t)tok * EMB);
    float4* d = (float4*)(d_Etgt + (size_t)n * EMB);
    d[threadIdx.x] = e[threadIdx.x];
}

// enc_score[n] = enc_out[n] . attnW[512:1024] + attnb   (one warp per row)
__global__ void score_kernel(const float* __restrict__ attnW, const float* __restrict__ attnb) {
    int warp = threadIdx.x >> 5, lane = threadIdx.x & 31;
    int n = blockIdx.x * 8 + warp;       // 0..2047
    const float* row = d_encout + (size_t)n * HID;
    const float* w2 = attnW + HID;
    float s = 0.0f;
    for (int i = lane; i < HID; i += 32) s += row[i] * w2[i];
#pragma unroll
    for (int o = 16; o > 0; o >>= 1) s += __shfl_xor_sync(0xffffffffu, s, o);
    if (lane == 0) d_score[n] = s + attnb[0];
}

// softmax over S per batch row + weighted sum of enc_out  -> ctx (constant over decoder steps)
__global__ void attn_ctx() {
    __shared__ float w_s[SS];
    __shared__ float inv_s;
    int b = blockIdx.x, tid = threadIdx.x;
    if (tid == 0) {
        float mx = -1e30f;
        for (int s = 0; s < SS; s++) mx = fmaxf(mx, d_score[b * SS + s]);
        float tot = 0.0f;
        for (int s = 0; s < SS; s++) {
            float e = expf(d_score[b * SS + s] - mx);
            w_s[s] = e;
            tot += e;
        }
        inv_s = 1.0f / tot;
    }
    __syncthreads();
    float inv = inv_s;
    for (int k = tid; k < HID; k += 128) {
        float acc = 0.0f;
        for (int s = 0; s < SS; s++)
            acc += w_s[s] * d_encout[(size_t)(b * SS + s) * HID + k];
        d_ctx[b * HID + k] = acc * inv;
    }
}

// ---------------- encoder LSTM step (both directions), one launch per t ----------------
// grid 128: blocks [0..63] fwd, [64..127] bwd. Each block: 8 hidden units (32 gate cols) x all 32 batch rows.
__global__ __launch_bounds__(256) void enc_step(
    const float* __restrict__ Whh_f,
    const float* __restrict__ Whh_b,
    int t)
{
    int bid = blockIdx.x;
    int dir = bid >> 6;
    int u0 = (bid & 63) << 3;
    const float* Whh = dir ? Whh_b : Whh_f;
    const float* X = dir ? d_Xb : d_Xf;
    int s = dir ? (SS - 1 - t) : t;     // input time index == store index, for both dirs
    int xrow = s * BB;
    const float* hbuf = d_henc[t & 1];
    float* hnext = d_henc[(t + 1) & 1];
    int hcol0 = dir << 9;

    __shared__ float sh_h[32][34];
    __shared__ float sh_w[32][34];
    __shared__ float g_s[32][32];

    int tid = threadIdx.x;
    int tx = tid & 15, ty = tid >> 4;
    int lr = tid >> 3;                 // 0..31
    int lk = (tid & 7) << 2;           // 0..28
    int wrow = ((lr >> 3) << 9) + u0 + (lr & 7);
    const float* hp = hbuf + lr * 1024 + hcol0 + lk;
    const float* wp = Whh + (size_t)wrow * HID + lk;

    float acc[2][2] = {{0.f, 0.f}, {0.f, 0.f}};
    for (int k0 = 0; k0 < HID; k0 += 32) {
        float4 hv = *(const float4*)(hp + k0);
        float4 wv = *(const float4*)(wp + k0);
        __syncthreads();
        sh_h[lk + 0][lr] = hv.x; sh_h[lk + 1][lr] = hv.y; sh_h[lk + 2][lr] = hv.z; sh_h[lk + 3][lr] = hv.w;
        sh_w[lk + 0][lr] = wv.x; sh_w[lk + 1][lr] = wv.y; sh_w[lk + 2][lr] = wv.z; sh_w[lk + 3][lr] = wv.w;
        __syncthreads();
#pragma unroll
        for (int kk = 0; kk < 32; kk++) {
            float2 a = *(const float2*)&sh_h[kk][ty << 1];
            float2 b = *(const float2*)&sh_w[kk][tx << 1];
            acc[0][0] += a.x * b.x; acc[0][1] += a.x * b.y;
            acc[1][0] += a.y * b.x; acc[1][1] += a.y * b.y;
        }
    }

    {
        int b0 = ty << 1, c0 = tx << 1;
#pragma unroll
        for (int r = 0; r < 2; r++)
#pragma unroll
            for (int cc = 0; cc < 2; cc++) {
                int bb = b0 + r, cg = c0 + cc;
                int gcol = ((cg >> 3) << 9) + u0 + (cg & 7);
                g_s[bb][cg] = acc[r][cc] + X[(size_t)(xrow + bb) * G4 + gcol];
            }
    }
    __syncthreads();
    {
        int bb = tid >> 3, u = tid & 7;
        float gi = g_s[bb][u];
        float gf = g_s[bb][8 + u];
        float gg = g_s[bb][16 + u];
        float go = g_s[bb][24 + u];
        int idx = bb * 1024 + hcol0 + u0 + u;
        float cold = d_cenc[idx];
        float cn = sigf(gf) * cold + sigf(gi) * tanhf(gg);
        float hn = sigf(go) * tanhf(cn);
        d_cenc[idx] = cn;
        hnext[idx] = hn;
        d_hcat[(size_t)(bb * SS + s) * 1024 + hcol0 + u0 + u] = hn;
    }
}

// ---------------- decoder LSTM step, one launch per t ----------------
// g = Xd[t] + Xc + h @ dWhh^T ; grid 64 blocks (8 units each).
__global__ __launch_bounds__(256) void dec_step(const float* __restrict__ dWhh, int t)
{
    int u0 = blockIdx.x << 3;
    const float* hbuf = d_hdec[t & 1];
    float* hnext = d_hdec[(t + 1) & 1];

    __shared__ float sh_h[32][34];
    __shared__ float sh_w[32][34];
    __shared__ float g_s[32][32];

    int tid = threadIdx.x;
    int tx = tid & 15, ty = tid >> 4;
    int lr = tid >> 3;
    int lk = (tid & 7) << 2;
    int wrow = ((lr >> 3) << 9) + u0 + (lr & 7);
    const float* hp = hbuf + lr * HID + lk;
    const float* wp = dWhh + (size_t)wrow * HID + lk;

    float acc[2][2] = {{0.f, 0.f}, {0.f, 0.f}};
    for (int k0 = 0; k0 < HID; k0 += 32) {
        float4 hv = *(const float4*)(hp + k0);
        float4 wv = *(const float4*)(wp + k0);
        __syncthreads();
        sh_h[lk + 0][lr] = hv.x; sh_h[lk + 1][lr] = hv.y; sh_h[lk + 2][lr] = hv.z; sh_h[lk + 3][lr] = hv.w;
        sh_w[lk + 0][lr] = wv.x; sh_w[lk + 1][lr] = wv.y; sh_w[lk + 2][lr] = wv.z; sh_w[lk + 3][lr] = wv.w;
        __syncthreads();
#pragma unroll
        for (int kk = 0; kk < 32; kk++) {
            float2 a = *(const float2*)&sh_h[kk][ty << 1];
            float2 b = *(const float2*)&sh_w[kk][tx << 1];
            acc[0][0] += a.x * b.x; acc[0][1] += a.x * b.y;
            acc[1][0] += a.y * b.x; acc[1][1] += a.y * b.y;
        }
    }

    {
        int b0 = ty << 1, c0 = tx << 1;
#pragma unroll
        for (int r = 0; r < 2; r++)
#pragma unroll
            for (int cc = 0; cc < 2; cc++) {
                int bb = b0 + r, cg = c0 + cc;
                int gcol = ((cg >> 3) << 9) + u0 + (cg & 7);
                g_s[bb][cg] = acc[r][cc]
                            + d_Xd[(size_t)(t * BB + bb) * G4 + gcol]
                            + d_Xc[bb * G4 + gcol];
            }
    }
    __syncthreads();
    {
        int bb = tid >> 3, u = tid & 7;
        float gi = g_s[bb][u];
        float gf = g_s[bb][8 + u];
        float gg = g_s[bb][16 + u];
        float go = g_s[bb][24 + u];
        int idx = bb * HID + u0 + u;
        float cold = d_cdec[idx];
        float cn = sigf(gf) * cold + sigf(gi) * tanhf(gg);
        float hn = sigf(go) * tanhf(cn);
        d_cdec[idx] = cn;
        hnext[idx] = hn;
        d_Hs[(size_t)(t * BB + bb) * HID + u0 + u] = hn;
    }
}

// ---------------- host launcher ----------------
extern "C" void kernel_launch(void* const* d_in, const int* in_sizes, int n_in,
                              void* d_out, int out_size)
{
    const int*   src     = (const int*)d_in[0];
    const int*   tgt     = (const int*)d_in[1];
    const float* enc_emb = (const float*)d_in[2];
    const float* dec_emb = (const float*)d_in[3];
    const float* Wih_f   = (const float*)d_in[4];
    const float* Whh_f   = (const float*)d_in[5];
    const float* b_f     = (const float*)d_in[6];
    const float* Wih_b   = (const float*)d_in[7];
    const float* Whh_b   = (const float*)d_in[8];
    const float* b_b     = (const float*)d_in[9];
    const float* encW    = (const float*)d_in[10];
    const float* encb    = (const float*)d_in[11];
    const float* dWih    = (const float*)d_in[12];
    const float* dWhh    = (const float*)d_in[13];
    const float* db      = (const float*)d_in[14];
    const float* attnW   = (const float*)d_in[15];
    const float* attnb   = (const float*)d_in[16];
    const float* projW   = (const float*)d_in[17];
    const float* projb   = (const float*)d_in[18];
    float* out = (float*)d_out;

    float *pEsrc, *pEtgt, *pXf, *pXb, *pXd, *pXc, *phcat, *phenc, *pcenc,
          *phdec, *pcdec, *pencout, *pctx, *pHs;
    int* prow;
    cudaGetSymbolAddress((void**)&pEsrc, d_Esrc);
    cudaGetSymbolAddress((void**)&pEtgt, d_Etgt);
    cudaGetSymbolAddress((void**)&pXf, d_Xf);
    cudaGetSymbolAddress((void**)&pXb, d_Xb);
    cudaGetSymbolAddress((void**)&pXd, d_Xd);
    cudaGetSymbolAddress((void**)&pXc, d_Xc);
    cudaGetSymbolAddress((void**)&phcat, d_hcat);
    cudaGetSymbolAddress((void**)&phenc, d_henc);   // buffer 0 base
    cudaGetSymbolAddress((void**)&pcenc, d_cenc);
    cudaGetSymbolAddress((void**)&phdec, d_hdec);   // buffer 0 base
    cudaGetSymbolAddress((void**)&pcdec, d_cdec);
    cudaGetSymbolAddress((void**)&pencout, d_encout);
    cudaGetSymbolAddress((void**)&pctx, d_ctx);
    cudaGetSymbolAddress((void**)&pHs, d_Hs);
    cudaGetSymbolAddress((void**)&prow, d_rowoff);

    // 0. reset recurrent state (deterministic every call)
    zero_f<<<(BB * 1024 + 255) / 256, 256>>>(phenc, BB * 1024);   // h_enc buf0 = 0
    zero_f<<<(BB * 1024 + 255) / 256, 256>>>(pcenc, BB * 1024);   // c_enc = 0
    zero_f<<<(BB * HID + 255) / 256, 256>>>(pcdec, BB * HID);     // c_dec = 0

    // 1. encoder input projections (hoisted out of the recurrence)
    gather_src<<<SS * BB, 64>>>(src, enc_emb);
    gemm64<<<dim3(G4 / 64, (SS * BB) / 64), 256>>>(pEsrc, EMB, Wih_f, EMB, b_f, pXf, G4, nullptr, SS * BB, EMB, 0);
    gemm64<<<dim3(G4 / 64, (SS * BB) / 64), 256>>>(pEsrc, EMB, Wih_b, EMB, b_b, pXb, G4, nullptr, SS * BB, EMB, 0);

    // 2. bidirectional encoder recurrence
    for (int t = 0; t < SS; t++)
        enc_step<<<128, 256>>>(Whh_f, Whh_b, t);

    // 3. enc_out = cat(hs_f, hs_b) @ encW^T + encb ; h0 = tanh(cat(hT) @ encW^T + encb)
    gemm64<<<dim3(HID / 64, (BB * SS) / 64), 256>>>(phcat, 1024, encW, 1024, encb, pencout, HID, nullptr, BB * SS, 1024, 0);
    gemm64<<<dim3(HID / 64, 1), 256>>>(phenc, 1024, encW, 1024, encb, phdec, HID, nullptr, BB, 1024, 1);

    // 4. attention is h-independent (softmax shift-invariance) -> constant ctx, then Xc = ctx@dWih[:,256:].T
    score_kernel<<<(BB * SS) / 8, 256>>>(attnW, attnb);
    attn_ctx<<<BB, 128>>>();
    gemm64<<<dim3(G4 / 64, 1), 256>>>(pctx, HID, dWih + EMB, EMB + HID, nullptr, pXc, G4, nullptr, BB, HID, 0);

    // 5. decoder input projections
    gather_tgt<<<TD * BB, 64>>>(tgt, dec_emb);
    gemm64<<<dim3(G4 / 64, (TD * BB + 63) / 64), 256>>>(pEtgt, EMB, dWih, EMB + HID, db, pXd, G4, nullptr, TD * BB, EMB, 0);

    // 6. decoder recurrence (projection deferred)
    for (int t = 0; t < TD; t++)
        dec_step<<<64, 256>>>(dWhh, t);

    // 7. one big vocabulary projection: out[b][t+1][:] = Hs[t*32+b] @ projW^T + projb ; out[:,0,:] = 0
    rowoff_kernel<<<(TD * BB + 255) / 256, 256>>>();
    zero_out0<<<(BB * VSZ + 255) / 256, 256>>>(out);
    gemm64<<<dim3(VSZ / 64, (TD * BB + 63) / 64), 256>>>(pHs, HID, projW, HID, projb, out, 0, prow, TD * BB, HID, 0);
}

// round 15
// speedup vs baseline: 1.4240x; 1.4240x over previous
#include <cuda_runtime.h>
#include <cuda_bf16.h>
#include <math.h>
#include <stdint.h>

// Problem dims
#define BB 32
#define SS 64
#define TT 64
#define HID 512
#define G4 2048      // 4*HID
#define EMB 256
#define VSZ 32000
#define TD 63        // decoder steps (T-1)

// ---------------- device scratch (static, no allocations) ----------------
__device__ float d_Esrc[SS*BB*EMB];
__device__ float d_Etgt[TD*BB*EMB];
__device__ float d_Xf[SS*BB*G4];
__device__ float d_Xb[SS*BB*G4];
__device__ float d_Xd[TD*BB*G4];
__device__ float d_Xc[BB*G4];
__device__ float d_hcat[BB*SS*2*HID];
__device__ float d_henc[2][BB*2*HID];
__device__ float d_cenc[BB*2*HID];
__device__ float d_hdec[2][BB*HID];
__device__ float d_cdec[BB*HID];
__device__ float d_encout[BB*SS*HID];
__device__ float d_score[BB*SS];
__device__ float d_ctx[BB*HID];
__device__ float d_Hs[TD*BB*HID];
// bf16 hi/lo split operands for the tensor-core projection
__device__ __nv_bfloat16 d_Whi[VSZ*HID];
__device__ __nv_bfloat16 d_Wlo[VSZ*HID];
__device__ __nv_bfloat16 d_Ahi[2048*HID];
__device__ __nv_bfloat16 d_Alo[2048*HID];

__device__ __forceinline__ float sigf(float x) { return 1.0f / (1.0f + expf(-x)); }

// ---------------- hi/lo bf16 prep kernels ----------------
__global__ void prep_W(const float* __restrict__ W) {
    int i = blockIdx.x * 256 + threadIdx.x;
    if (i < VSZ * HID) {
        float x = W[i];
        __nv_bfloat16 h = __float2bfloat16(x);
        d_Whi[i] = h;
        d_Wlo[i] = __float2bfloat16(x - __bfloat162float(h));
    }
}
__global__ void prep_A() {
    int i = blockIdx.x * 256 + threadIdx.x;   // covers 2048*512
    float x = (i < TD * BB * HID) ? d_Hs[i] : 0.0f;
    __nv_bfloat16 h = __float2bfloat16(x);
    d_Ahi[i] = h;
    d_Alo[i] = __float2bfloat16(x - __bfloat162float(h));
}

// ---------------- tensor-core projection via baseline-PTX mma.sync ----------------
// out[b][t+1][n] = Hs[t*32+b] . projW[n] + projb[n]
// CTA tile 128(M) x 128(N), 8 warps in 2x4, warp tile 64x32, K chunk 32.
// 3-term bf16 hi/lo split: Ah*Bh + Ah*Bl + Al*Bh (fp32-class accuracy).

#define MMA16816(d, a, b) \
    asm volatile("mma.sync.aligned.m16n8k16.row.col.f32.bf16.bf16.f32 " \
        "{%0,%1,%2,%3}, {%4,%5,%6,%7}, {%8,%9}, {%0,%1,%2,%3};" \
        : "+f"((d)[0]), "+f"((d)[1]), "+f"((d)[2]), "+f"((d)[3]) \
        : "r"((a)[0]), "r"((a)[1]), "r"((a)[2]), "r"((a)[3]), \
          "r"((b)[0]), "r"((b)[1]))

#define SM_STRIDE 40   // 32 k-cols + 8 pad (bf16 units)

__device__ __forceinline__ uint32_t lds32(const __nv_bfloat16* p) {
    return *(const uint32_t*)p;
}

__global__ void __launch_bounds__(256, 2) proj_mma(const float* __restrict__ projb,
                                                   float* __restrict__ out) {
    __shared__ __align__(16) __nv_bfloat16 sAh[128 * SM_STRIDE];
    __shared__ __align__(16) __nv_bfloat16 sAl[128 * SM_STRIDE];
    __shared__ __align__(16) __nv_bfloat16 sBh[128 * SM_STRIDE];
    __shared__ __align__(16) __nv_bfloat16 sBl[128 * SM_STRIDE];

    int tid = threadIdx.x;
    int ntile = blockIdx.x, mtile = blockIdx.y;    // ntile fast -> B swept L2-resident
    int wid = tid >> 5, lane = tid & 31;
    int warp_m = wid >> 2, warp_n = wid & 3;
    int grp = lane >> 2, tg2 = (lane & 3) << 1;

    float acc[4][4][4];
#pragma unroll
    for (int i = 0; i < 4; i++)
#pragma unroll
        for (int j = 0; j < 4; j++)
#pragma unroll
            for (int r = 0; r < 4; r++) acc[i][j][r] = 0.0f;

    const __nv_bfloat16* Agh = d_Ahi + (size_t)(mtile << 7) * HID;
    const __nv_bfloat16* Agl = d_Alo + (size_t)(mtile << 7) * HID;
    const __nv_bfloat16* Bgh = d_Whi + (size_t)(ntile << 7) * HID;
    const __nv_bfloat16* Bgl = d_Wlo + (size_t)(ntile << 7) * HID;

    for (int kc = 0; kc < 16; kc++) {
        __syncthreads();
#pragma unroll
        for (int it = 0; it < 2; it++) {
            int idx = tid + (it << 8);          // 0..511
            int row = idx >> 2;                  // 0..127
            int c8 = idx & 3;                    // uint4 index in 32-col row
            int so = row * SM_STRIDE + (c8 << 3);
            size_t go = (size_t)row * HID + (kc << 5) + (c8 << 3);
            *(uint4*)&sAh[so] = *(const uint4*)(Agh + go);
            *(uint4*)&sAl[so] = *(const uint4*)(Agl + go);
            *(uint4*)&sBh[so] = *(const uint4*)(Bgh + go);
            *(uint4*)&sBl[so] = *(const uint4*)(Bgl + go);
        }
        __syncthreads();

#pragma unroll
        for (int ks = 0; ks < 32; ks += 16) {
            int kcol = ks + tg2;
            uint32_t bh[4][2], bl[4][2], af[4][4];
#pragma unroll
            for (int j = 0; j < 4; j++) {
                int nr = (warp_n << 5) + (j << 3) + grp;
                bh[j][0] = lds32(&sBh[nr * SM_STRIDE + kcol]);
                bh[j][1] = lds32(&sBh[nr * SM_STRIDE + kcol + 8]);
                bl[j][0] = lds32(&sBl[nr * SM_STRIDE + kcol]);
                bl[j][1] = lds32(&sBl[nr * SM_STRIDE + kcol + 8]);
            }
#pragma unroll
            for (int i = 0; i < 4; i++) {
                int mr = (warp_m << 6) + (i << 4) + grp;
                af[i][0] = lds32(&sAh[mr * SM_STRIDE + kcol]);
                af[i][1] = lds32(&sAh[(mr + 8) * SM_STRIDE + kcol]);
                af[i][2] = lds32(&sAh[mr * SM_STRIDE + kcol + 8]);
                af[i][3] = lds32(&sAh[(mr + 8) * SM_STRIDE + kcol + 8]);
            }
#pragma unroll
            for (int i = 0; i < 4; i++)
#pragma unroll
                for (int j = 0; j < 4; j++) MMA16816(acc[i][j], af[i], bh[j]);
#pragma unroll
            for (int i = 0; i < 4; i++)
#pragma unroll
                for (int j = 0; j < 4; j++) MMA16816(acc[i][j], af[i], bl[j]);
            // reuse af registers for A-lo
#pragma unroll
            for (int i = 0; i < 4; i++) {
                int mr = (warp_m << 6) + (i << 4) + grp;
                af[i][0] = lds32(&sAl[mr * SM_STRIDE + kcol]);
                af[i][1] = lds32(&sAl[(mr + 8) * SM_STRIDE + kcol]);
                af[i][2] = lds32(&sAl[mr * SM_STRIDE + kcol + 8]);
                af[i][3] = lds32(&sAl[(mr + 8) * SM_STRIDE + kcol + 8]);
            }
#pragma unroll
            for (int i = 0; i < 4; i++)
#pragma unroll
                for (int j = 0; j < 4; j++) MMA16816(acc[i][j], af[i], bh[j]);
        }
    }

    // epilogue: scatter rows into out[b][t+1][:], add bias
    int n0 = (ntile << 7) + (warp_n << 5) + tg2;
    int m0 = (mtile << 7) + (warp_m << 6) + grp;
#pragma unroll
    for (int i = 0; i < 4; i++) {
#pragma unroll
        for (int half = 0; half < 2; half++) {
            int g = m0 + (i << 4) + (half << 3);
            if (g < TD * BB) {
                int t = g >> 5, b = g & 31;
                float* dst = out + (size_t)b * TT * VSZ + (size_t)(t + 1) * VSZ;
#pragma unroll
                for (int j = 0; j < 4; j++) {
                    int n = n0 + (j << 3);
                    float2 pb = *(const float2*)(projb + n);
                    float2 v;
                    v.x = acc[i][j][(half << 1) + 0] + pb.x;
                    v.y = acc[i][j][(half << 1) + 1] + pb.y;
                    *(float2*)(dst + n) = v;
                }
            }
        }
    }
}

// ---------------- generic 64x64 tiled GEMM: C = A @ W^T (+bias) ----------------
__global__ __launch_bounds__(256) void gemm64(
    const float* __restrict__ A, int lda,
    const float* __restrict__ W, int ldw,
    const float* __restrict__ bias,
    float* __restrict__ C, int ldc,
    int M, int K, int act)
{
    __shared__ float As[16][68];
    __shared__ float Bs[16][68];
    int tid = threadIdx.x;
    int m0 = blockIdx.y << 6;
    int n0 = blockIdx.x << 6;
    int lrow = tid >> 2;
    int lk   = (tid & 3) << 2;
    int tx = tid & 15, ty = tid >> 4;

    float acc[4][4];
#pragma unroll
    for (int i = 0; i < 4; i++)
#pragma unroll
        for (int j = 0; j < 4; j++) acc[i][j] = 0.0f;

    const float* Ap = A + (size_t)(m0 + lrow) * lda + lk;
    const float* Wp = W + (size_t)(n0 + lrow) * ldw + lk;
    bool aok = (m0 + lrow) < M;

    for (int k0 = 0; k0 < K; k0 += 16) {
        float4 av = aok ? *(const float4*)(Ap + k0) : make_float4(0.f, 0.f, 0.f, 0.f);
        float4 bv = *(const float4*)(Wp + k0);
        __syncthreads();
        As[lk + 0][lrow] = av.x; As[lk + 1][lrow] = av.y; As[lk + 2][lrow] = av.z; As[lk + 3][lrow] = av.w;
        Bs[lk + 0][lrow] = bv.x; Bs[lk + 1][lrow] = bv.y; Bs[lk + 2][lrow] = bv.z; Bs[lk + 3][lrow] = bv.w;
        __syncthreads();
#pragma unroll
        for (int kk = 0; kk < 16; kk++) {
            float4 a = *(const float4*)&As[kk][ty << 2];
            float4 b = *(const float4*)&Bs[kk][tx << 2];
            acc[0][0] += a.x*b.x; acc[0][1] += a.x*b.y; acc[0][2] += a.x*b.z; acc[0][3] += a.x*b.w;
            acc[1][0] += a.y*b.x; acc[1][1] += a.y*b.y; acc[1][2] += a.y*b.z; acc[1][3] += a.y*b.w;
            acc[2][0] += a.z*b.x; acc[2][1] += a.z*b.y; acc[2][2] += a.z*b.z; acc[2][3] += a.z*b.w;
            acc[3][0] += a.w*b.x; acc[3][1] += a.w*b.y; acc[3][2] += a.w*b.z; acc[3][3] += a.w*b.w;
        }
    }

    int n = n0 + (tx << 2);
    float4 bz = make_float4(0.f, 0.f, 0.f, 0.f);
    if (bias) bz = *(const float4*)(bias + n);
#pragma unroll
    for (int r = 0; r < 4; r++) {
        int m = m0 + (ty << 2) + r;
        if (m < M) {
            float4 v;
            v.x = acc[r][0] + bz.x;
            v.y = acc[r][1] + bz.y;
            v.z = acc[r][2] + bz.z;
            v.w = acc[r][3] + bz.w;
            if (act) { v.x = tanhf(v.x); v.y = tanhf(v.y); v.z = tanhf(v.z); v.w = tanhf(v.w); }
            *(float4*)(C + (size_t)m * (size_t)ldc + n) = v;
        }
    }
}

// ---------------- small helper kernels ----------------
__global__ void zero_f(float* p, int n) {
    int i = blockIdx.x * blockDim.x + threadIdx.x;
    if (i < n) p[i] = 0.0f;
}

__global__ void zero_out0(float* out) {
    int i = blockIdx.x * blockDim.x + threadIdx.x;
    if (i < BB * VSZ) {
        int b = i / VSZ, v = i - b * VSZ;
        out[(size_t)b * TT * VSZ + v] = 0.0f;
    }
}

__global__ void gather_src(const int* __restrict__ src, const float* __restrict__ emb) {
    int n = blockIdx.x;
    int s = n >> 5, b = n & 31;
    int tok = src[b * SS + s];
    const float4* e = (const float4*)(emb + (size_t)tok * EMB);
    float4* d = (float4*)(d_Esrc + (size_t)n * EMB);
    d[threadIdx.x] = e[threadIdx.x];
}

__global__ void gather_tgt(const int* __restrict__ tgt, const float* __restrict__ emb) {
    int n = blockIdx.x;
    int t = n >> 5, b = n & 31;
    int tok = tgt[b * TT + t];
    const float4* e = (const float4*)(emb + (size_t)tok * EMB);
    float4* d = (float4*)(d_Etgt + (size_t)n * EMB);
    d[threadIdx.x] = e[threadIdx.x];
}

__global__ void score_kernel(const float* __restrict__ attnW, const float* __restrict__ attnb) {
    int warp = threadIdx.x >> 5, lane = threadIdx.x & 31;
    int n = blockIdx.x * 8 + warp;
    const float* row = d_encout + (size_t)n * HID;
    const float* w2 = attnW + HID;
    float s = 0.0f;
    for (int i = lane; i < HID; i += 32) s += row[i] * w2[i];
#pragma unroll
    for (int o = 16; o > 0; o >>= 1) s += __shfl_xor_sync(0xffffffffu, s, o);
    if (lane == 0) d_score[n] = s + attnb[0];
}

__global__ void attn_ctx() {
    __shared__ float w_s[SS];
    __shared__ float inv_s;
    int b = blockIdx.x, tid = threadIdx.x;
    if (tid == 0) {
        float mx = -1e30f;
        for (int s = 0; s < SS; s++) mx = fmaxf(mx, d_score[b * SS + s]);
        float tot = 0.0f;
        for (int s = 0; s < SS; s++) {
            float e = expf(d_score[b * SS + s] - mx);
            w_s[s] = e;
            tot += e;
        }
        inv_s = 1.0f / tot;
    }
    __syncthreads();
    float inv = inv_s;
    for (int k = tid; k < HID; k += 128) {
        float acc = 0.0f;
        for (int s = 0; s < SS; s++)
            acc += w_s[s] * d_encout[(size_t)(b * SS + s) * HID + k];
        d_ctx[b * HID + k] = acc * inv;
    }
}

// ---------------- encoder LSTM step (both directions), one launch per t ----------------
__global__ __launch_bounds__(256) void enc_step(
    const float* __restrict__ Whh_f,
    const float* __restrict__ Whh_b,
    int t)
{
    int bid = blockIdx.x;
    int dir = bid >> 6;
    int u0 = (bid & 63) << 3;
    const float* Whh = dir ? Whh_b : Whh_f;
    const float* X = dir ? d_Xb : d_Xf;
    int s = dir ? (SS - 1 - t) : t;
    int xrow = s * BB;
    const float* hbuf = d_henc[t & 1];
    float* hnext = d_henc[(t + 1) & 1];
    int hcol0 = dir << 9;

    __shared__ float sh_h[32][34];
    __shared__ float sh_w[32][34];
    __shared__ float g_s[32][32];

    int tid = threadIdx.x;
    int tx = tid & 15, ty = tid >> 4;
    int lr = tid >> 3;
    int lk = (tid & 7) << 2;
    int wrow = ((lr >> 3) << 9) + u0 + (lr & 7);
    const float* hp = hbuf + lr * 1024 + hcol0 + lk;
    const float* wp = Whh + (size_t)wrow * HID + lk;

    float acc[2][2] = {{0.f, 0.f}, {0.f, 0.f}};
    for (int k0 = 0; k0 < HID; k0 += 32) {
        float4 hv = *(const float4*)(hp + k0);
        float4 wv = *(const float4*)(wp + k0);
        __syncthreads();
        sh_h[lk + 0][lr] = hv.x; sh_h[lk + 1][lr] = hv.y; sh_h[lk + 2][lr] = hv.z; sh_h[lk + 3][lr] = hv.w;
        sh_w[lk + 0][lr] = wv.x; sh_w[lk + 1][lr] = wv.y; sh_w[lk + 2][lr] = wv.z; sh_w[lk + 3][lr] = wv.w;
        __syncthreads();
#pragma unroll
        for (int kk = 0; kk < 32; kk++) {
            float2 a = *(const float2*)&sh_h[kk][ty << 1];
            float2 b = *(const float2*)&sh_w[kk][tx << 1];
            acc[0][0] += a.x * b.x; acc[0][1] += a.x * b.y;
            acc[1][0] += a.y * b.x; acc[1][1] += a.y * b.y;
        }
    }

    {
        int b0 = ty << 1, c0 = tx << 1;
#pragma unroll
        for (int r = 0; r < 2; r++)
#pragma unroll
            for (int cc = 0; cc < 2; cc++) {
                int bb = b0 + r, cg = c0 + cc;
                int gcol = ((cg >> 3) << 9) + u0 + (cg & 7);
                g_s[bb][cg] = acc[r][cc] + X[(size_t)(xrow + bb) * G4 + gcol];
            }
    }
    __syncthreads();
    {
        int bb = tid >> 3, u = tid & 7;
        float gi = g_s[bb][u];
        float gf = g_s[bb][8 + u];
        float gg = g_s[bb][16 + u];
        float go = g_s[bb][24 + u];
        int idx = bb * 1024 + hcol0 + u0 + u;
        float cold = d_cenc[idx];
        float cn = sigf(gf) * cold + sigf(gi) * tanhf(gg);
        float hn = sigf(go) * tanhf(cn);
        d_cenc[idx] = cn;
        hnext[idx] = hn;
        d_hcat[(size_t)(bb * SS + s) * 1024 + hcol0 + u0 + u] = hn;
    }
}

// ---------------- decoder LSTM step, one launch per t ----------------
__global__ __launch_bounds__(256) void dec_step(const float* __restrict__ dWhh, int t)
{
    int u0 = blockIdx.x << 3;
    const float* hbuf = d_hdec[t & 1];
    float* hnext = d_hdec[(t + 1) & 1];

    __shared__ float sh_h[32][34];
    __shared__ float sh_w[32][34];
    __shared__ float g_s[32][32];

    int tid = threadIdx.x;
    int tx = tid & 15, ty = tid >> 4;
    int lr = tid >> 3;
    int lk = (tid & 7) << 2;
    int wrow = ((lr >> 3) << 9) + u0 + (lr & 7);
    const float* hp = hbuf + lr * HID + lk;
    const float* wp = dWhh + (size_t)wrow * HID + lk;

    float acc[2][2] = {{0.f, 0.f}, {0.f, 0.f}};
    for (int k0 = 0; k0 < HID; k0 += 32) {
        float4 hv = *(const float4*)(hp + k0);
        float4 wv = *(const float4*)(wp + k0);
        __syncthreads();
        sh_h[lk + 0][lr] = hv.x; sh_h[lk + 1][lr] = hv.y; sh_h[lk + 2][lr] = hv.z; sh_h[lk + 3][lr] = hv.w;
        sh_w[lk + 0][lr] = wv.x; sh_w[lk + 1][lr] = wv.y; sh_w[lk + 2][lr] = wv.z; sh_w[lk + 3][lr] = wv.w;
        __syncthreads();
#pragma unroll
        for (int kk = 0; kk < 32; kk++) {
            float2 a = *(const float2*)&sh_h[kk][ty << 1];
            float2 b = *(const float2*)&sh_w[kk][tx << 1];
            acc[0][0] += a.x * b.x; acc[0][1] += a.x * b.y;
            acc[1][0] += a.y * b.x; acc[1][1] += a.y * b.y;
        }
    }

    {
        int b0 = ty << 1, c0 = tx << 1;
#pragma unroll
        for (int r = 0; r < 2; r++)
#pragma unroll
            for (int cc = 0; cc < 2; cc++) {
                int bb = b0 + r, cg = c0 + cc;
                int gcol = ((cg >> 3) << 9) + u0 + (cg & 7);
                g_s[bb][cg] = acc[r][cc]
                            + d_Xd[(size_t)(t * BB + bb) * G4 + gcol]
                            + d_Xc[bb * G4 + gcol];
            }
    }
    __syncthreads();
    {
        int bb = tid >> 3, u = tid & 7;
        float gi = g_s[bb][u];
        float gf = g_s[bb][8 + u];
        float gg = g_s[bb][16 + u];
        float go = g_s[bb][24 + u];
        int idx = bb * HID + u0 + u;
        float cold = d_cdec[idx];
        float cn = sigf(gf) * cold + sigf(gi) * tanhf(gg);
        float hn = sigf(go) * tanhf(cn);
        d_cdec[idx] = cn;
        hnext[idx] = hn;
        d_Hs[(size_t)(t * BB + bb) * HID + u0 + u] = hn;
    }
}

// ---------------- host launcher ----------------
extern "C" void kernel_launch(void* const* d_in, const int* in_sizes, int n_in,
                              void* d_out, int out_size)
{
    const int*   src     = (const int*)d_in[0];
    const int*   tgt     = (const int*)d_in[1];
    const float* enc_emb = (const float*)d_in[2];
    const float* dec_emb = (const float*)d_in[3];
    const float* Wih_f   = (const float*)d_in[4];
    const float* Whh_f   = (const float*)d_in[5];
    const float* b_f     = (const float*)d_in[6];
    const float* Wih_b   = (const float*)d_in[7];
    const float* Whh_b   = (const float*)d_in[8];
    const float* b_b     = (const float*)d_in[9];
    const float* encW    = (const float*)d_in[10];
    const float* encb    = (const float*)d_in[11];
    const float* dWih    = (const float*)d_in[12];
    const float* dWhh    = (const float*)d_in[13];
    const float* db      = (const float*)d_in[14];
    const float* attnW   = (const float*)d_in[15];
    const float* attnb   = (const float*)d_in[16];
    const float* projW   = (const float*)d_in[17];
    const float* projb   = (const float*)d_in[18];
    float* out = (float*)d_out;

    float *pEsrc, *pEtgt, *pXf, *pXb, *pXd, *pXc, *phcat, *phenc, *pcenc,
          *phdec, *pcdec, *pencout, *pctx;
    cudaGetSymbolAddress((void**)&pEsrc, d_Esrc);
    cudaGetSymbolAddress((void**)&pEtgt, d_Etgt);
    cudaGetSymbolAddress((void**)&pXf, d_Xf);
    cudaGetSymbolAddress((void**)&pXb, d_Xb);
    cudaGetSymbolAddress((void**)&pXd, d_Xd);
    cudaGetSymbolAddress((void**)&pXc, d_Xc);
    cudaGetSymbolAddress((void**)&phcat, d_hcat);
    cudaGetSymbolAddress((void**)&phenc, d_henc);
    cudaGetSymbolAddress((void**)&pcenc, d_cenc);
    cudaGetSymbolAddress((void**)&phdec, d_hdec);
    cudaGetSymbolAddress((void**)&pcdec, d_cdec);
    cudaGetSymbolAddress((void**)&pencout, d_encout);
    cudaGetSymbolAddress((void**)&pctx, d_ctx);

    // 0. reset recurrent state + weight hi/lo split (independent of pipeline, launch early)
    zero_f<<<(BB * 1024 + 255) / 256, 256>>>(phenc, BB * 1024);
    zero_f<<<(BB * 1024 + 255) / 256, 256>>>(pcenc, BB * 1024);
    zero_f<<<(BB * HID + 255) / 256, 256>>>(pcdec, BB * HID);
    prep_W<<<(VSZ * HID + 255) / 256, 256>>>(projW);

    // 1. encoder input projections (hoisted out of the recurrence)
    gather_src<<<SS * BB, 64>>>(src, enc_emb);
    gemm64<<<dim3(G4 / 64, (SS * BB) / 64), 256>>>(pEsrc, EMB, Wih_f, EMB, b_f, pXf, G4, SS * BB, EMB, 0);
    gemm64<<<dim3(G4 / 64, (SS * BB) / 64), 256>>>(pEsrc, EMB, Wih_b, EMB, b_b, pXb, G4, SS * BB, EMB, 0);

    // 2. bidirectional encoder recurrence
    for (int t = 0; t < SS; t++)
        enc_step<<<128, 256>>>(Whh_f, Whh_b, t);

    // 3. enc_out + decoder h0
    gemm64<<<dim3(HID / 64, (BB * SS) / 64), 256>>>(phcat, 1024, encW, 1024, encb, pencout, HID, BB * SS, 1024, 0);
    gemm64<<<dim3(HID / 64, 1), 256>>>(phenc, 1024, encW, 1024, encb, phdec, HID, BB, 1024, 1);

    // 4. h-independent attention -> constant ctx -> Xc
    score_kernel<<<(BB * SS) / 8, 256>>>(attnW, attnb);
    attn_ctx<<<BB, 128>>>();
    gemm64<<<dim3(G4 / 64, 1), 256>>>(pctx, HID, dWih + EMB, EMB + HID, nullptr, pXc, G4, BB, HID, 0);

    // 5. decoder input projections
    gather_tgt<<<TD * BB, 64>>>(tgt, dec_emb);
    gemm64<<<dim3(G4 / 64, (TD * BB + 63) / 64), 256>>>(pEtgt, EMB, dWih, EMB + HID, db, pXd, G4, TD * BB, EMB, 0);

    // 6. decoder recurrence (projection deferred)
    for (int t = 0; t < TD; t++)
        dec_step<<<64, 256>>>(dWhh, t);

    // 7. tensor-core vocabulary projection via mma.sync (bf16 hi/lo 3-term)
    prep_A<<<(2048 * HID + 255) / 256, 256>>>();
    zero_out0<<<(BB * VSZ + 255) / 256, 256>>>(out);
    proj_mma<<<dim3(VSZ / 128, 16), 256>>>(projb, out);
}